// round 8
// baseline (speedup 1.0000x reference)
#include <cuda_runtime.h>
#include <cstdint>

// Problem constants (fixed by the dataset)
#define BATCH   16
#define C_IN    64
#define HH      32
#define WW      32
#define C_OUT   128
#define PH      34          // padded plane height (1 + 32 + 1)
#define PW      40          // padded plane width: 4 left + 32 + 4 right (16B-aligned interior)
#define PLANE   (PH*PW)     // 1360 floats
#define PLANE4  (PLANE/4)   // 340 float4
#define BUF     (2*PLANE)   // one batch = 2 planes = 2720 floats
#define NB      2           // batches per block

// 16B async copy global->shared (LDGSTS.128)
__device__ __forceinline__ void cp16(float* dst_smem, const float* src) {
    uint32_t d = (uint32_t)__cvta_generic_to_shared(dst_smem);
    asm volatile("cp.async.cg.shared.global [%0], [%1], 16;\n" :: "r"(d), "l"(src));
}

// gate(a,b) = c0 + ca*a + cb*b + cab*a*b, factored to 3 FMAs:
//   fma(fma(cab,b,ca), a, fma(cb,b,c0))
__device__ __forceinline__ float gate3(const float4 k, float a, float b) {
    return fmaf(fmaf(k.w, b, k.y), a, fmaf(k.z, b, k.x));
}

// ---------------------------------------------------------------------------
// One block per (oc, batch-pair). NB=2 cp.async double-buffered staging,
// decode/softmax by threads 0..7 overlapped with border fill and staging
// latency (no early syncthreads), hot loop 8 LDS + 21 FMA + 1 STG per pixel
// with immediate-offset addressing. 8 blocks/SM -> single wave, 64 warps/SM.
// ---------------------------------------------------------------------------
__global__ void __launch_bounds__(256, 8)
tree_kernel(const float* __restrict__ x,
            const float* __restrict__ w,
            const int*   __restrict__ leaf_idx,
            float*       __restrict__ out)
{
    __shared__ __align__(16) float sm[NB * BUF];   // 21760 B
    __shared__ __align__(16) float s_coef[16];     // 4 gates x {c0,ca,cb,cab}
    __shared__ int   s_off[8];                     // leaf word offsets

    const int blk = blockIdx.x;          // 0..1023
    const int oc  = blk & (C_OUT - 1);
    const int bg  = blk >> 7;            // 0..7 -> batches 2*bg, 2*bg+1
    const int tid = threadIdx.x;

    // --- channels: broadcast loads by ALL threads (no smem round-trip) ----
    const int chA = __ldg(&leaf_idx[oc * 8 + 0]) / 9;
    const int chB = __ldg(&leaf_idx[oc * 8 + 4]) / 9;

    // --- leaf offsets: threads 0..7 decode into smem (read after 1st sync)-
    if (tid < 8) {
        int idx = __ldg(&leaf_idx[oc * 8 + tid]);
        int ch  = idx / 9;
        int pos = idx - ch * 9;
        int ki  = pos / 3;
        int kj  = pos - ki * 3;
        s_off[tid] = (tid >> 2) * PLANE + ki * PW + kj;
    }

    // --- softmax -> 4 affine coefficients, threads 0..3 (gate = tid) -----
    // op order: 0, ab, a-ab, a, b-ab, b, s-2ab, s-ab, 1-(s-ab), 1-(s-2ab),
    //           1-b, 1-b+ab, 1-a, 1-a+ab, 1-ab, 1
    if (tid < 4) {
        const float T0[16]  = {0,0,0,0,0,0,0,0, 1, 1, 1, 1, 1, 1, 1, 1};
        const float TA[16]  = {0,0,1,1,0,0,1,1,-1,-1, 0, 0,-1,-1, 0, 0};
        const float TB[16]  = {0,0,0,0,1,1,1,1,-1,-1,-1,-1, 0, 0, 0, 0};
        const float TAB[16] = {0,1,-1,0,-1,0,-2,-1, 1, 2, 0, 1, 0, 1,-1, 0};

        const float* wp = w + (oc * 7 + tid) * 16;   // weights [C_out, 7, 16]

        float m = wp[0];
        #pragma unroll
        for (int i = 1; i < 16; i++) m = fmaxf(m, wp[i]);

        float e[16];
        float s = 0.f;
        #pragma unroll
        for (int i = 0; i < 16; i++) { e[i] = __expf(wp[i] - m); s += e[i]; }
        float inv = 1.f / s;

        float c0 = 0.f, ca = 0.f, cb = 0.f, cab = 0.f;
        #pragma unroll
        for (int i = 0; i < 16; i++) {
            c0  += e[i] * T0[i];
            ca  += e[i] * TA[i];
            cb  += e[i] * TB[i];
            cab += e[i] * TAB[i];
        }
        s_coef[tid * 4 + 0] = c0 * inv;
        s_coef[tid * 4 + 1] = ca * inv;
        s_coef[tid * 4 + 2] = cb * inv;
        s_coef[tid * 4 + 3] = cab * inv;
    }

    // --- zero the border words read by the gather (overlaps LDG latency) --
    // Per plane, 84 float4 slots padded to 128: k<68 -> side col-groups {0,9}
    // of rows 0..33; 68..75 -> row 0 cols 4..35; 76..83 -> row 33 cols 4..35.
    // Border 16B chunks are disjoint from the cp.async interior chunks, so no
    // ordering between this fill and the async stage is required.
    {
        float4 z = make_float4(0.f, 0.f, 0.f, 0.f);
        float4* smv = (float4*)sm;
        #pragma unroll
        for (int i = 0; i < 2; i++) {
            int t = tid + i * 256;       // 0..511 = 4 planes x 128 slots
            int q = t >> 7;              // plane 0..3 (contiguous)
            int k = t & 127;
            if (k < 84) {
                int f4;
                if (k < 68)      f4 = (k >> 1) * 10 + ((k & 1) ? 9 : 0);
                else if (k < 76) f4 = k - 67;            // row 0, groups 1..8
                else             f4 = 330 + (k - 75);    // row 33, groups 1..8
                smv[q * PLANE4 + f4] = z;
            }
        }
    }

    // --- issue async stages for both batches (one commit group per batch) --
    // Plane select is compile-time per cp16: i=0 -> plane A, i=1 -> plane B.
    {
        float* dstA = sm + ((tid >> 3) + 1) * PW + 4 + (tid & 7) * 4;
        const float* xb = x + ((size_t)(bg * NB) * C_IN + chA) * (HH * WW);
        const int dAB = (chB - chA) * (HH * WW);       // plane A -> plane B
        #pragma unroll
        for (int u = 0; u < NB; u++) {
            const float* src = xb + (size_t)u * (C_IN * HH * WW) + tid * 4;
            cp16(dstA + u * BUF,         src);
            cp16(dstA + u * BUF + PLANE, src + dAB);
            asm volatile("cp.async.commit_group;\n");
        }
    }

    // --- batch 0 ready (1 group still pending); s_off/s_coef visible ------
    asm volatile("cp.async.wait_group 1;\n");
    __syncthreads();

    // Coefficients to registers (4x LDS.128)
    const float4* cf = (const float4*)s_coef;
    const float4 k0 = cf[0], k1 = cf[1], k2 = cf[2], k3 = cf[3];

    // Per-thread base pixel: y = tid>>5, x = tid&31 -> padded col x+3
    const int pb0 = (tid >> 5) * PW + (tid & 31) + 3;
    const int o0 = s_off[0] + pb0, o1 = s_off[1] + pb0;
    const int o2 = s_off[2] + pb0, o3 = s_off[3] + pb0;
    const int o4 = s_off[4] + pb0, o5 = s_off[5] + pb0;
    const int o6 = s_off[6] + pb0, o7 = s_off[7] + pb0;

    float* ob = out + ((size_t)(bg * NB) * C_OUT + oc) * (HH * WW) + tid;

    #pragma unroll
    for (int u = 0; u < NB; u++) {
        if (u == 1) {
            asm volatile("cp.async.wait_group 0;\n");
            __syncthreads();
            ob += (size_t)C_OUT * (HH * WW);
        }
        const float* bp = sm + u * BUF;

        #pragma unroll
        for (int t = 0; t < 4; t++) {
            const int d = t * 8 * PW;        // +8 rows per step (256 pixels)

            float l0 = bp[o0 + d], l1 = bp[o1 + d];
            float l2 = bp[o2 + d], l3 = bp[o3 + d];
            float l4 = bp[o4 + d], l5 = bp[o5 + d];
            float l6 = bp[o6 + d], l7 = bp[o7 + d];

            // level 0: weight rows 0,1,2,3
            float m0 = gate3(k0, l0, l1);
            float m1 = gate3(k1, l2, l3);
            float m2 = gate3(k2, l4, l5);
            float m3 = gate3(k3, l6, l7);
            // level 1: rows 1,2
            float n0 = gate3(k1, m0, m1);
            float n1 = gate3(k2, m2, m3);
            // level 2: row 3
            float r  = gate3(k3, n0, n1);

            ob[t * 256] = r;
        }
    }
}

extern "C" void kernel_launch(void* const* d_in, const int* in_sizes, int n_in,
                              void* d_out, int out_size)
{
    const float* x   = (const float*)d_in[0];          // [16,64,32,32]
    const float* w   = (const float*)d_in[1];          // [128,7,16]
    const int*   idx = (const int*)d_in[2];            // [128,8]
    float*       out = (float*)d_out;                  // [16,128,32,32]

    tree_kernel<<<(BATCH / NB) * C_OUT, 256>>>(x, w, idx, out);
}

// round 9
// speedup vs baseline: 1.0029x; 1.0029x over previous
#include <cuda_runtime.h>
#include <cstdint>

// Problem constants (fixed by the dataset)
#define BATCH   16
#define C_IN    64
#define HH      32
#define WW      32
#define C_OUT   128
#define PH      34          // padded plane height (1 + 32 + 1)
#define PW      40          // padded plane width: 4 left + 32 + 4 right (16B-aligned interior)
#define PLANE   (PH*PW)     // 1360 floats
#define PLANE4  (PLANE/4)   // 340 float4
#define BUF     (2*PLANE)   // one batch = 2 planes = 2720 floats
#define NB      2           // batches per block

// 16B async copy global->shared (LDGSTS.128)
__device__ __forceinline__ void cp16(float* dst_smem, const float* src) {
    uint32_t d = (uint32_t)__cvta_generic_to_shared(dst_smem);
    asm volatile("cp.async.cg.shared.global [%0], [%1], 16;\n" :: "r"(d), "l"(src));
}

// gate(a,b) = c0 + ca*a + cb*b + cab*a*b, factored to 3 FMAs:
//   fma(fma(cab,b,ca), a, fma(cb,b,c0))
__device__ __forceinline__ float gate3(const float4 k, float a, float b) {
    return fmaf(fmaf(k.w, b, k.y), a, fmaf(k.z, b, k.x));
}

// ---------------------------------------------------------------------------
// One block per (oc, batch-pair). Both batches staged with cp.async up front,
// ONE wait + ONE barrier for the whole kernel, then 8 fully-unrolled
// independent (u,t) iterations (8 LDS + 21 FMA + 1 STG each, all-immediate
// offsets) that ptxas can software-pipeline freely.
// ---------------------------------------------------------------------------
__global__ void __launch_bounds__(256, 8)
tree_kernel(const float* __restrict__ x,
            const float* __restrict__ w,
            const int*   __restrict__ leaf_idx,
            float*       __restrict__ out)
{
    __shared__ __align__(16) float sm[NB * BUF];   // 21760 B
    __shared__ __align__(16) float s_coef[16];     // 4 gates x {c0,ca,cb,cab}
    __shared__ int   s_off[8];                     // leaf word offsets

    const int blk = blockIdx.x;          // 0..1023
    const int oc  = blk & (C_OUT - 1);
    const int bg  = blk >> 7;            // 0..7 -> batches 2*bg, 2*bg+1
    const int tid = threadIdx.x;

    // --- channels: broadcast loads by ALL threads (no smem round-trip) ----
    const int chA = __ldg(&leaf_idx[oc * 8 + 0]) / 9;
    const int chB = __ldg(&leaf_idx[oc * 8 + 4]) / 9;

    // --- leaf offsets: threads 0..7 decode into smem (read after the sync)-
    if (tid < 8) {
        int idx = __ldg(&leaf_idx[oc * 8 + tid]);
        int ch  = idx / 9;
        int pos = idx - ch * 9;
        int ki  = pos / 3;
        int kj  = pos - ki * 3;
        s_off[tid] = (tid >> 2) * PLANE + ki * PW + kj;
    }

    // --- softmax -> 4 affine coefficients, threads 0..3 (gate = tid) -----
    // op order: 0, ab, a-ab, a, b-ab, b, s-2ab, s-ab, 1-(s-ab), 1-(s-2ab),
    //           1-b, 1-b+ab, 1-a, 1-a+ab, 1-ab, 1
    if (tid < 4) {
        const float T0[16]  = {0,0,0,0,0,0,0,0, 1, 1, 1, 1, 1, 1, 1, 1};
        const float TA[16]  = {0,0,1,1,0,0,1,1,-1,-1, 0, 0,-1,-1, 0, 0};
        const float TB[16]  = {0,0,0,0,1,1,1,1,-1,-1,-1,-1, 0, 0, 0, 0};
        const float TAB[16] = {0,1,-1,0,-1,0,-2,-1, 1, 2, 0, 1, 0, 1,-1, 0};

        const float* wp = w + (oc * 7 + tid) * 16;   // weights [C_out, 7, 16]

        float m = wp[0];
        #pragma unroll
        for (int i = 1; i < 16; i++) m = fmaxf(m, wp[i]);

        float e[16];
        float s = 0.f;
        #pragma unroll
        for (int i = 0; i < 16; i++) { e[i] = __expf(wp[i] - m); s += e[i]; }
        float inv = 1.f / s;

        float c0 = 0.f, ca = 0.f, cb = 0.f, cab = 0.f;
        #pragma unroll
        for (int i = 0; i < 16; i++) {
            c0  += e[i] * T0[i];
            ca  += e[i] * TA[i];
            cb  += e[i] * TB[i];
            cab += e[i] * TAB[i];
        }
        s_coef[tid * 4 + 0] = c0 * inv;
        s_coef[tid * 4 + 1] = ca * inv;
        s_coef[tid * 4 + 2] = cb * inv;
        s_coef[tid * 4 + 3] = cab * inv;
    }

    // --- zero the border words read by the gather (overlaps LDG latency) --
    // Per plane, 84 float4 slots padded to 128: k<68 -> side col-groups {0,9}
    // of rows 0..33; 68..75 -> row 0 cols 4..35; 76..83 -> row 33 cols 4..35.
    // Border 16B chunks are disjoint from the cp.async interior chunks, so no
    // ordering between this fill and the async stage is required.
    {
        float4 z = make_float4(0.f, 0.f, 0.f, 0.f);
        float4* smv = (float4*)sm;
        #pragma unroll
        for (int i = 0; i < 2; i++) {
            int t = tid + i * 256;       // 0..511 = 4 planes x 128 slots
            int q = t >> 7;              // plane 0..3 (contiguous)
            int k = t & 127;
            if (k < 84) {
                int f4;
                if (k < 68)      f4 = (k >> 1) * 10 + ((k & 1) ? 9 : 0);
                else if (k < 76) f4 = k - 67;            // row 0, groups 1..8
                else             f4 = 330 + (k - 75);    // row 33, groups 1..8
                smv[q * PLANE4 + f4] = z;
            }
        }
    }

    // --- issue async stages for both batches (single commit group) --------
    {
        float* dstA = sm + ((tid >> 3) + 1) * PW + 4 + (tid & 7) * 4;
        const float* xb = x + ((size_t)(bg * NB) * C_IN + chA) * (HH * WW);
        const int dAB = (chB - chA) * (HH * WW);       // plane A -> plane B
        #pragma unroll
        for (int u = 0; u < NB; u++) {
            const float* src = xb + (size_t)u * (C_IN * HH * WW) + tid * 4;
            cp16(dstA + u * BUF,         src);
            cp16(dstA + u * BUF + PLANE, src + dAB);
        }
        asm volatile("cp.async.commit_group;\n");
    }

    // --- ONE wait + ONE barrier for the whole kernel ----------------------
    asm volatile("cp.async.wait_group 0;\n");
    __syncthreads();

    // Coefficients to registers (4x LDS.128)
    const float4* cf = (const float4*)s_coef;
    const float4 k0 = cf[0], k1 = cf[1], k2 = cf[2], k3 = cf[3];

    // Per-thread base pixel: y = tid>>5, x = tid&31 -> padded col x+3
    const int pb0 = (tid >> 5) * PW + (tid & 31) + 3;
    const int o0 = s_off[0] + pb0, o1 = s_off[1] + pb0;
    const int o2 = s_off[2] + pb0, o3 = s_off[3] + pb0;
    const int o4 = s_off[4] + pb0, o5 = s_off[5] + pb0;
    const int o6 = s_off[6] + pb0, o7 = s_off[7] + pb0;

    float* ob = out + ((size_t)(bg * NB) * C_OUT + oc) * (HH * WW) + tid;

    // 8 fully independent iterations; all offsets compile-time immediates.
    #pragma unroll
    for (int it = 0; it < 8; it++) {
        const int u = it >> 2;               // batch   (0,0,0,0,1,1,1,1)
        const int t = it & 3;                // row-tile (0..3)
        const int d = u * BUF + t * 8 * PW;  // smem word offset (constant)

        float l0 = sm[o0 + d], l1 = sm[o1 + d];
        float l2 = sm[o2 + d], l3 = sm[o3 + d];
        float l4 = sm[o4 + d], l5 = sm[o5 + d];
        float l6 = sm[o6 + d], l7 = sm[o7 + d];

        // level 0: weight rows 0,1,2,3
        float m0 = gate3(k0, l0, l1);
        float m1 = gate3(k1, l2, l3);
        float m2 = gate3(k2, l4, l5);
        float m3 = gate3(k3, l6, l7);
        // level 1: rows 1,2
        float n0 = gate3(k1, m0, m1);
        float n1 = gate3(k2, m2, m3);
        // level 2: row 3
        float r  = gate3(k3, n0, n1);

        ob[u * (C_OUT * HH * WW) + t * 256] = r;   // constant byte offset
    }
}

extern "C" void kernel_launch(void* const* d_in, const int* in_sizes, int n_in,
                              void* d_out, int out_size)
{
    const float* x   = (const float*)d_in[0];          // [16,64,32,32]
    const float* w   = (const float*)d_in[1];          // [128,7,16]
    const int*   idx = (const int*)d_in[2];            // [128,8]
    float*       out = (float*)d_out;                  // [16,128,32,32]

    tree_kernel<<<(BATCH / NB) * C_OUT, 256>>>(x, w, idx, out);
}

// round 10
// speedup vs baseline: 1.0238x; 1.0208x over previous
#include <cuda_runtime.h>
#include <cstdint>

// Problem constants (fixed by the dataset)
#define BATCH   16
#define C_IN    64
#define HH      32
#define WW      32
#define C_OUT   128
#define NB      2            // batches per block
#define RPW     40           // padded row width: 4 left + 32 + 4 right
#define WROWS   6            // input rows staged per warp (4 outputs + halo)
#define WPLANE  (WROWS*RPW)  // 240 floats: one channel slab per warp
#define WBATCH  (2*WPLANE)   // 480: both channels, one batch
#define WREG    (NB*WBATCH)  // 960: one warp's full region

// 16B async copy global->shared (LDGSTS.128)
__device__ __forceinline__ void cp16(float* dst_smem, const float* src) {
    uint32_t d = (uint32_t)__cvta_generic_to_shared(dst_smem);
    asm volatile("cp.async.cg.shared.global [%0], [%1], 16;\n" :: "r"(d), "l"(src));
}

// gate(a,b) = c0 + ca*a + cb*b + cab*a*b, factored to 3 FMAs
__device__ __forceinline__ float gate3(const float4 k, float a, float b) {
    return fmaf(fmaf(k.w, b, k.y), a, fmaf(k.z, b, k.x));
}

// ---------------------------------------------------------------------------
// One block per (oc, batch-pair); one WARP per 4 output rows. Each warp
// stages its own 6-row x 2-channel x 2-batch window with cp.async and waits
// ONLY on its own groups (no block barrier between staging and compute), so
// warps de-phase by memory return order and LDS bursts spread out in time.
// ---------------------------------------------------------------------------
__global__ void __launch_bounds__(256, 7)
tree_kernel(const float* __restrict__ x,
            const float* __restrict__ w,
            const int*   __restrict__ leaf_idx,
            float*       __restrict__ out)
{
    __shared__ __align__(16) float sm[8 * WREG];   // 30720 B
    __shared__ __align__(16) float s_coef[16];     // 4 gates x {c0,ca,cb,cab}
    __shared__ int   s_off[8];                     // leaf offsets within a warp slab

    const int blk  = blockIdx.x;         // 0..1023
    const int oc   = blk & (C_OUT - 1);
    const int bg2  = (blk >> 7) * NB;    // first batch of this block's pair
    const int tid  = threadIdx.x;
    const int warp = tid >> 5;
    const int lane = tid & 31;

    // --- channels: broadcast loads by ALL threads --------------------------
    const int chA = __ldg(&leaf_idx[oc * 8 + 0]) / 9;
    const int chB = __ldg(&leaf_idx[oc * 8 + 4]) / 9;

    // --- leaf offsets within a warp slab: threads 0..7 ---------------------
    if (tid < 8) {
        int idx = __ldg(&leaf_idx[oc * 8 + tid]);
        int ch  = idx / 9;
        int pos = idx - ch * 9;
        int ki  = pos / 3;
        int kj  = pos - ki * 3;
        s_off[tid] = (tid >> 2) * WPLANE + ki * RPW + kj + 3;
    }

    // --- softmax -> 4 affine coefficients, threads 0..3 (gate = tid) -------
    // op order: 0, ab, a-ab, a, b-ab, b, s-2ab, s-ab, 1-(s-ab), 1-(s-2ab),
    //           1-b, 1-b+ab, 1-a, 1-a+ab, 1-ab, 1
    if (tid < 4) {
        const float T0[16]  = {0,0,0,0,0,0,0,0, 1, 1, 1, 1, 1, 1, 1, 1};
        const float TA[16]  = {0,0,1,1,0,0,1,1,-1,-1, 0, 0,-1,-1, 0, 0};
        const float TB[16]  = {0,0,0,0,1,1,1,1,-1,-1,-1,-1, 0, 0, 0, 0};
        const float TAB[16] = {0,1,-1,0,-1,0,-2,-1, 1, 2, 0, 1, 0, 1,-1, 0};

        const float* wp = w + (oc * 7 + tid) * 16;   // weights [C_out, 7, 16]

        float m = wp[0];
        #pragma unroll
        for (int i = 1; i < 16; i++) m = fmaxf(m, wp[i]);

        float e[16];
        float s = 0.f;
        #pragma unroll
        for (int i = 0; i < 16; i++) { e[i] = __expf(wp[i] - m); s += e[i]; }
        float inv = 1.f / s;

        float c0 = 0.f, ca = 0.f, cb = 0.f, cab = 0.f;
        #pragma unroll
        for (int i = 0; i < 16; i++) {
            c0  += e[i] * T0[i];
            ca  += e[i] * TA[i];
            cb  += e[i] * TB[i];
            cab += e[i] * TAB[i];
        }
        s_coef[tid * 4 + 0] = c0 * inv;
        s_coef[tid * 4 + 1] = ca * inv;
        s_coef[tid * 4 + 2] = cb * inv;
        s_coef[tid * 4 + 3] = cab * inv;
    }

    float* const wbase = sm + warp * WREG;

    // --- side pads: zero cols 0-3 and 36-39 of all 24 warp rows ------------
    {
        float4 z = make_float4(0.f, 0.f, 0.f, 0.f);
        #pragma unroll
        for (int i = 0; i < 2; i++) {
            int tsk = lane + i * 32;              // 0..47
            if (tsk < 48) {
                int side = tsk & 1;
                int r24  = tsk >> 1;              // 0..23
                int pu   = (r24 * 43) >> 8;       // /6  -> 0..3 = (u<<1)|p
                int lr   = r24 - 6 * pu;
                *(float4*)(wbase + (pu >> 1) * WBATCH + (pu & 1) * WPLANE
                           + lr * RPW + side * 36) = z;
            }
        }
    }

    // --- per-warp row staging: 6 rows x 2 ch x 8 chunks per batch ----------
    // grow = warp*4 - 1 + lr ; out-of-range rows are zero-filled via STS.
    {
        float4 z = make_float4(0.f, 0.f, 0.f, 0.f);
        #pragma unroll
        for (int u = 0; u < NB; u++) {
            #pragma unroll
            for (int i = 0; i < 3; i++) {
                int tsk = lane + i * 32;          // 0..95
                int c   = tsk & 7;
                int r12 = tsk >> 3;               // 0..11
                int p   = (r12 * 43) >> 8;        // /6 -> plane 0/1
                int lr  = r12 - 6 * p;
                int grow = (warp << 2) - 1 + lr;
                float* dst = wbase + u * WBATCH + p * WPLANE + lr * RPW + 4 + c * 4;
                if ((unsigned)grow < 32u) {
                    const float* src = x
                        + (((size_t)(bg2 + u) * C_IN + (p ? chB : chA)) << 10)
                        + grow * 32 + c * 4;
                    cp16(dst, src);
                } else {
                    *(float4*)dst = z;
                }
            }
            asm volatile("cp.async.commit_group;\n");
        }
    }

    // --- ONE cheap barrier: publishes s_off/s_coef (and STS zeros). -------
    // Does NOT wait for cp.async data; warps de-phase on their own waits.
    __syncthreads();

    // Coefficients to registers (4x LDS.128)
    const float4* cf = (const float4*)s_coef;
    const float4 k0 = cf[0], k1 = cf[1], k2 = cf[2], k3 = cf[3];

    // 8 leaf base pointers within this warp's slab (lane = output column)
    const float* p0 = wbase + s_off[0] + lane;
    const float* p1 = wbase + s_off[1] + lane;
    const float* p2 = wbase + s_off[2] + lane;
    const float* p3 = wbase + s_off[3] + lane;
    const float* p4 = wbase + s_off[4] + lane;
    const float* p5 = wbase + s_off[5] + lane;
    const float* p6 = wbase + s_off[6] + lane;
    const float* p7 = wbase + s_off[7] + lane;

    float* ob = out + ((size_t)bg2 * C_OUT + oc) * (HH * WW)
                    + (warp << 2) * WW + lane;

    #pragma unroll
    for (int u = 0; u < NB; u++) {
        if (u == 0) { asm volatile("cp.async.wait_group 1;\n"); __syncwarp(); }
        else        { asm volatile("cp.async.wait_group 0;\n"); __syncwarp(); }

        #pragma unroll
        for (int lr = 0; lr < 4; lr++) {
            const int d = u * WBATCH + lr * RPW;   // compile-time after unroll

            float l0 = p0[d], l1 = p1[d];
            float l2 = p2[d], l3 = p3[d];
            float l4 = p4[d], l5 = p5[d];
            float l6 = p6[d], l7 = p7[d];

            // level 0: weight rows 0,1,2,3
            float m0 = gate3(k0, l0, l1);
            float m1 = gate3(k1, l2, l3);
            float m2 = gate3(k2, l4, l5);
            float m3 = gate3(k3, l6, l7);
            // level 1: rows 1,2
            float n0 = gate3(k1, m0, m1);
            float n1 = gate3(k2, m2, m3);
            // level 2: row 3
            float r  = gate3(k3, n0, n1);

            ob[u * (C_OUT * HH * WW) + lr * WW] = r;   // constant offsets
        }
    }
}

extern "C" void kernel_launch(void* const* d_in, const int* in_sizes, int n_in,
                              void* d_out, int out_size)
{
    const float* x   = (const float*)d_in[0];          // [16,64,32,32]
    const float* w   = (const float*)d_in[1];          // [128,7,16]
    const int*   idx = (const int*)d_in[2];            // [128,8]
    float*       out = (float*)d_out;                  // [16,128,32,32]

    tree_kernel<<<(BATCH / NB) * C_OUT, 256>>>(x, w, idx, out);
}